// round 1
// baseline (speedup 1.0000x reference)
#include <cuda_runtime.h>
#include <math.h>

#define NN 100000
#define NE 1600000
#define DD 128
#define HH 128
#define HO 64
#define NCLS 10
#define NG 128

// ---------------- device scratch (static, no runtime alloc) ----------------
__device__ int   g_is64_edge;
__device__ int   g_is64_batch;
__device__ int   g_src[NE];
__device__ int   g_dst[NE];
__device__ int   g_col[NE];
__device__ int   g_batch[NN];
__device__ int   g_deg[NN];
__device__ float g_dis[NN];
__device__ int   g_rowptr[NN + 1];
__device__ int   g_cursor[NN];
__device__ int   g_bsum[128];
__device__ float g_W12[DD * HH];
__device__ float g_b12[HH];
__device__ float g_h2[(size_t)NN * HH];   // x@W12 + b12
__device__ float g_h3[(size_t)NN * HH];   // after agg1 + bias + dropout + relu
__device__ float g_h4[(size_t)NN * HO];   // h3@conv2_w
__device__ float g_pool[NG * HO];
__device__ int   g_cnt[NG];

// ---------------- dtype detection (int64 vs int32 index arrays) ------------
__global__ void k_detect(const unsigned int* __restrict__ ew, long esz,
                         const unsigned int* __restrict__ bw, long bsz) {
    __shared__ int fe, fb;
    if (threadIdx.x == 0) { fe = 0; fb = 0; }
    __syncthreads();
    for (int i = threadIdx.x; i < 4096; i += blockDim.x) {
        // odd int32-word positions within [0, esz): for int64 data these are
        // high words (always 0 since values < 2^31); for int32 data they are
        // random node ids (virtually never all zero).
        long idx = 1 + 2 * ((long)i * ((esz - 2) / 2) / 4096);
        if (idx >= esz) idx = esz - 1;
        if (!(idx & 1)) idx--;
        if (idx >= 0 && idx < esz && ew[idx] != 0u) atomicOr(&fe, 1);
        // batch is sorted 0..127; sample odd words in the upper half.
        long j = bsz / 2 + ((long)i * (bsz / 2) / 4096);
        if (!(j & 1)) j++;
        if (j < bsz && bw[j] != 0u) atomicOr(&fb, 1);
    }
    __syncthreads();
    if (threadIdx.x == 0) {
        g_is64_edge  = (fe == 0);
        g_is64_batch = (fb == 0);
    }
}

__global__ void k_convert(const void* __restrict__ ep, const void* __restrict__ bp) {
    int e64 = g_is64_edge, b64 = g_is64_batch;
    long stride = (long)gridDim.x * blockDim.x;
    long i0 = (long)blockIdx.x * blockDim.x + threadIdx.x;
    if (e64) {
        const long long* p = (const long long*)ep;
        for (long i = i0; i < NE; i += stride) {
            g_src[i] = (int)p[i];
            g_dst[i] = (int)p[NE + i];
        }
    } else {
        const int* p = (const int*)ep;
        for (long i = i0; i < NE; i += stride) {
            g_src[i] = p[i];
            g_dst[i] = p[NE + i];
        }
    }
    if (b64) {
        const long long* p = (const long long*)bp;
        for (long i = i0; i < NN; i += stride) g_batch[i] = (int)p[i];
    } else {
        const int* p = (const int*)bp;
        for (long i = i0; i < NN; i += stride) g_batch[i] = p[i];
    }
}

// ---------------- init / histogram / scan / fill ----------------------------
__global__ void k_init() {
    int i = blockIdx.x * blockDim.x + threadIdx.x;
    int st = gridDim.x * blockDim.x;
    for (int j = i; j < NN; j += st) g_deg[j] = 0;
    for (int j = i; j < NG * HO; j += st) g_pool[j] = 0.f;
    for (int j = i; j < NG; j += st) g_cnt[j] = 0;
}

__global__ void k_hist() {
    long i0 = (long)blockIdx.x * blockDim.x + threadIdx.x;
    long st = (long)gridDim.x * blockDim.x;
    for (long i = i0; i < NE; i += st) atomicAdd(&g_deg[g_dst[i]], 1);
    for (long i = i0; i < NN; i += st) atomicAdd(&g_cnt[g_batch[i]], 1);
}

__global__ void k_reduce() {
    __shared__ int s[1024];
    int i = blockIdx.x * 1024 + threadIdx.x;
    s[threadIdx.x] = (i < NN) ? g_deg[i] : 0;
    __syncthreads();
    for (int o = 512; o > 0; o >>= 1) {
        if (threadIdx.x < o) s[threadIdx.x] += s[threadIdx.x + o];
        __syncthreads();
    }
    if (threadIdx.x == 0) g_bsum[blockIdx.x] = s[0];
}

__global__ void k_scanoff() {
    const int nb = (NN + 1023) / 1024;
    int run = 0;
    for (int b = 0; b < nb; b++) {
        int t = g_bsum[b];
        g_bsum[b] = run;
        run += t;
    }
}

__global__ void k_scanwrite() {
    __shared__ int s[1024];
    int t = threadIdx.x;
    int i = blockIdx.x * 1024 + t;
    int v = (i < NN) ? g_deg[i] : 0;
    s[t] = v;
    __syncthreads();
    for (int o = 1; o < 1024; o <<= 1) {
        int add = (t >= o) ? s[t - o] : 0;
        __syncthreads();
        if (t >= o) s[t] += add;
        __syncthreads();
    }
    if (i < NN) {
        int excl = s[t] - v + g_bsum[blockIdx.x];
        g_rowptr[i] = excl;
        g_cursor[i] = excl;
        g_dis[i] = rsqrtf((float)(v + 1));  // +1 for the self loop
    }
    if (i == 0) g_rowptr[NN] = NE;
}

__global__ void k_fill() {
    long i0 = (long)blockIdx.x * blockDim.x + threadIdx.x;
    long st = (long)gridDim.x * blockDim.x;
    for (long e = i0; e < NE; e += st) {
        int d = g_dst[e];
        int p = atomicAdd(&g_cursor[d], 1);
        g_col[p] = g_src[e];
    }
}

// ---------------- fold lin1 into conv1: W12 = lin1_w @ conv1_w --------------
__global__ void k_fold(const float* __restrict__ l1w, const float* __restrict__ l1b,
                       const float* __restrict__ c1w) {
    int idx = blockIdx.x * blockDim.x + threadIdx.x;
    if (idx < DD * HH) {
        int k = idx / HH, m = idx % HH;
        float s = 0.f;
        for (int j = 0; j < DD; j++) s += l1w[k * DD + j] * c1w[j * HH + m];
        g_W12[idx] = s;
    } else if (idx < DD * HH + HH) {
        int m = idx - DD * HH;
        float s = 0.f;
        for (int j = 0; j < DD; j++) s += l1b[j] * c1w[j * HH + m];
        g_b12[m] = s;
    }
}

// ---------------- tiled fp32 GEMM: out[n][MOUT] = A[n][128] @ W + bias ------
// MODE 1: A = param x,  W = g_W12,  bias = g_b12,  out = g_h2
// MODE 2: A = g_h3,     W = param,  bias = none,   out = g_h4
template <int MOUT, int ROWS, int MODE>
__global__ void __launch_bounds__(256) k_gemm(const float* __restrict__ Aparam,
                                              const float* __restrict__ Wparam,
                                              int nrows) {
    constexpr int KC = 32;
    constexpr int NCG = MOUT / 8;
    constexpr int NRG = 256 / NCG;
    static_assert(NRG * 4 == ROWS, "tile mismatch");
    __shared__ float Xs[ROWS][KC + 1];
    __shared__ float Ws[KC][MOUT];

    const float* A = (MODE == 1) ? Aparam : g_h3;
    const float* W = (MODE == 1) ? (const float*)g_W12 : Wparam;
    float* out = (MODE == 1) ? g_h2 : g_h4;

    int tid = threadIdx.x;
    int cg = tid % NCG, rg = tid / NCG;
    int row0 = blockIdx.x * ROWS;

    float acc[4][8];
#pragma unroll
    for (int r = 0; r < 4; r++)
#pragma unroll
        for (int c = 0; c < 8; c++) acc[r][c] = 0.f;

    for (int k0 = 0; k0 < DD; k0 += KC) {
#pragma unroll
        for (int idx = tid; idx < ROWS * KC / 4; idx += 256) {
            int r = idx / (KC / 4), j = idx % (KC / 4);
            int gr = row0 + r;
            float4 v = make_float4(0.f, 0.f, 0.f, 0.f);
            if (gr < nrows) v = *(const float4*)&A[(size_t)gr * DD + k0 + j * 4];
            Xs[r][j * 4 + 0] = v.x;
            Xs[r][j * 4 + 1] = v.y;
            Xs[r][j * 4 + 2] = v.z;
            Xs[r][j * 4 + 3] = v.w;
        }
#pragma unroll
        for (int idx = tid; idx < KC * MOUT / 4; idx += 256) {
            int kk = idx / (MOUT / 4), j = idx % (MOUT / 4);
            *(float4*)&Ws[kk][j * 4] = *(const float4*)&W[(size_t)(k0 + kk) * MOUT + j * 4];
        }
        __syncthreads();
#pragma unroll
        for (int k = 0; k < KC; k++) {
            float aa[4];
#pragma unroll
            for (int r = 0; r < 4; r++) aa[r] = Xs[rg * 4 + r][k];
            float4 b0 = *(float4*)&Ws[k][cg * 8];
            float4 b1 = *(float4*)&Ws[k][cg * 8 + 4];
            float bb[8] = {b0.x, b0.y, b0.z, b0.w, b1.x, b1.y, b1.z, b1.w};
#pragma unroll
            for (int r = 0; r < 4; r++)
#pragma unroll
                for (int c = 0; c < 8; c++) acc[r][c] += aa[r] * bb[c];
        }
        __syncthreads();
    }

    float bv[8];
#pragma unroll
    for (int c = 0; c < 8; c++) bv[c] = (MODE == 1) ? g_b12[cg * 8 + c] : 0.f;
#pragma unroll
    for (int r = 0; r < 4; r++) {
        int row = row0 + rg * 4 + r;
        if (row < nrows) {
            float4 o0 = make_float4(acc[r][0] + bv[0], acc[r][1] + bv[1],
                                    acc[r][2] + bv[2], acc[r][3] + bv[3]);
            float4 o1 = make_float4(acc[r][4] + bv[4], acc[r][5] + bv[5],
                                    acc[r][6] + bv[6], acc[r][7] + bv[7]);
            *(float4*)&out[(size_t)row * MOUT + cg * 8] = o0;
            *(float4*)&out[(size_t)row * MOUT + cg * 8 + 4] = o1;
        }
    }
}

// ---------------- aggregation 1 (gather, 128 feats) + bias/dropout/relu -----
__global__ void k_agg1(const float* __restrict__ c1b, const float* __restrict__ du) {
    int w = (blockIdx.x * blockDim.x + threadIdx.x) >> 5;
    int lane = threadIdx.x & 31;
    if (w >= NN) return;
    int node = w;
    float di = g_dis[node];
    size_t base = (size_t)node * HH + lane * 4;
    float4 v = *(const float4*)&g_h2[base];
    float ws = di * di;
    float ax = ws * v.x, ay = ws * v.y, az = ws * v.z, aw = ws * v.w;
    int b = g_rowptr[node], e = g_rowptr[node + 1];
    for (int t = b; t < e; t++) {
        int s = g_col[t];
        float wn = di * g_dis[s];
        float4 u = *(const float4*)&g_h2[(size_t)s * HH + lane * 4];
        ax += wn * u.x;
        ay += wn * u.y;
        az += wn * u.z;
        aw += wn * u.w;
    }
    int c0 = lane * 4;
    float4 bb = *(const float4*)&c1b[c0];
    float4 dd = *(const float4*)&du[(size_t)node * DD + c0];
    float o[4] = {ax + bb.x, ay + bb.y, az + bb.z, aw + bb.w};
    float d4[4] = {dd.x, dd.y, dd.z, dd.w};
#pragma unroll
    for (int q = 0; q < 4; q++) {
        float val = (d4[q] >= 0.5f) ? o[q] * 2.f : 0.f;
        o[q] = fmaxf(val, 0.f);
    }
    *(float4*)&g_h3[base] = make_float4(o[0], o[1], o[2], o[3]);
}

// ---------------- aggregation 2 (64 feats) + bias + fused mean-pool sums ----
__global__ void k_agg2(const float* __restrict__ c2b) {
    int w = (blockIdx.x * blockDim.x + threadIdx.x) >> 5;
    int lane = threadIdx.x & 31;
    if (w >= NN) return;
    int node = w;
    float di = g_dis[node];
    size_t base = (size_t)node * HO + lane * 2;
    float2 v = *(const float2*)&g_h4[base];
    float ws = di * di;
    float a0 = ws * v.x, a1 = ws * v.y;
    int b = g_rowptr[node], e = g_rowptr[node + 1];
    for (int t = b; t < e; t++) {
        int s = g_col[t];
        float wn = di * g_dis[s];
        float2 u = *(const float2*)&g_h4[(size_t)s * HO + lane * 2];
        a0 += wn * u.x;
        a1 += wn * u.y;
    }
    int c0 = lane * 2;
    a0 += c2b[c0];
    a1 += c2b[c0 + 1];
    int g = g_batch[node];
    atomicAdd(&g_pool[g * HO + c0], a0);
    atomicAdd(&g_pool[g * HO + c0 + 1], a1);
}

// ---------------- final: (pool / cnt) @ lin2_w + lin2_b ---------------------
__global__ void k_final(const float* __restrict__ w2, const float* __restrict__ b2,
                        float* __restrict__ out) {
    int idx = blockIdx.x * blockDim.x + threadIdx.x;
    if (idx >= NG * NCLS) return;
    int g = idx / NCLS, c = idx % NCLS;
    float cnt = (float)g_cnt[g];
    if (cnt < 1.f) cnt = 1.f;
    float inv = 1.f / cnt;
    float s = 0.f;
    for (int j = 0; j < HO; j++) s += g_pool[g * HO + j] * inv * w2[j * NCLS + c];
    out[idx] = s + b2[c];
}

// ---------------- host launcher --------------------------------------------
extern "C" void kernel_launch(void* const* d_in, const int* in_sizes, int n_in,
                              void* d_out, int out_size) {
    const float* x = (const float*)d_in[0];
    const void* edge = d_in[1];
    const void* batch = d_in[2];
    // num_graphs (scalar) may or may not be materialized as an input
    int off = (n_in >= 13 && in_sizes[3] == 1) ? 1 : 0;
    const float* drop_u = (const float*)d_in[3 + off];
    const float* l1w = (const float*)d_in[4 + off];
    const float* l1b = (const float*)d_in[5 + off];
    const float* c1w = (const float*)d_in[6 + off];
    const float* c1b = (const float*)d_in[7 + off];
    const float* c2w = (const float*)d_in[8 + off];
    const float* c2b = (const float*)d_in[9 + off];
    const float* l2w = (const float*)d_in[10 + off];
    const float* l2b = (const float*)d_in[11 + off];
    float* out = (float*)d_out;
    long esz = in_sizes[1];
    long bsz = in_sizes[2];

    k_detect<<<1, 256>>>((const unsigned int*)edge, esz, (const unsigned int*)batch, bsz);
    k_convert<<<2048, 256>>>(edge, batch);
    k_init<<<256, 256>>>();
    k_hist<<<2048, 256>>>();
    k_reduce<<<(NN + 1023) / 1024, 1024>>>();
    k_scanoff<<<1, 1>>>();
    k_scanwrite<<<(NN + 1023) / 1024, 1024>>>();
    k_fill<<<2048, 256>>>();
    k_fold<<<(DD * HH + HH + 255) / 256, 256>>>(l1w, l1b, c1w);
    k_gemm<HH, 64, 1><<<(NN + 63) / 64, 256>>>(x, nullptr, NN);
    k_agg1<<<(NN + 7) / 8, 256>>>(c1b, drop_u);
    k_gemm<HO, 128, 2><<<(NN + 127) / 128, 256>>>(nullptr, c2w, NN);
    k_agg2<<<(NN + 7) / 8, 256>>>(c2b);
    k_final<<<(NG * NCLS + 255) / 256, 256>>>(l2w, l2b, out);
    (void)out_size;
}

// round 4
// speedup vs baseline: 1.3556x; 1.3556x over previous
#include <cuda_runtime.h>
#include <math.h>

#define NN 100000
#define NE 1600000
#define DD 128
#define HH 128
#define HO 64
#define NCLS 10
#define NG 128

// ---------------- device scratch (static, no runtime alloc) ----------------
__device__ int   g_is64_edge;
__device__ int   g_is64_batch;
__device__ int   g_src[NE];
__device__ int   g_dst[NE];
__device__ int   g_col[NE];
__device__ int   g_batch[NN];
__device__ int   g_deg[NN];
__device__ float g_dis[NN];
__device__ int   g_rowptr[NN + 1];
__device__ int   g_cursor[NN];
__device__ int   g_bsum[128];
__device__ float g_W12[DD * HH];
__device__ float g_b12[HH];
__device__ float g_h2[(size_t)NN * HH];   // (x@W12 + b12) * dis[row]  (prescaled)
__device__ float g_h3[(size_t)NN * HH];   // after agg1 + bias + dropout + relu
__device__ float g_h4[(size_t)NN * HO];   // (h3@conv2_w) * dis[row]   (prescaled)
__device__ float g_pool[NG * HO];

// ---------------- f32x2 helpers (FFMA2 on sm_103a) --------------------------
__device__ __forceinline__ unsigned long long pack2(float a) {
    unsigned long long r;
    asm("mov.b64 %0, {%1, %1};" : "=l"(r) : "f"(a));
    return r;
}
__device__ __forceinline__ void fma2(unsigned long long& d, unsigned long long a,
                                     unsigned long long b) {
    asm("fma.rn.f32x2 %0, %1, %2, %0;" : "+l"(d) : "l"(a), "l"(b));
}
__device__ __forceinline__ void unpack2(unsigned long long v, float& lo, float& hi) {
    asm("mov.b64 {%0, %1}, %2;" : "=f"(lo), "=f"(hi) : "l"(v));
}

// ---------------- dtype detection (int64 vs int32 index arrays) ------------
__global__ void k_detect(const unsigned int* __restrict__ ew, long esz,
                         const unsigned int* __restrict__ bw, long bsz) {
    __shared__ int fe, fb;
    if (threadIdx.x == 0) { fe = 0; fb = 0; }
    __syncthreads();
    for (int i = threadIdx.x; i < 4096; i += blockDim.x) {
        long idx = 1 + 2 * ((long)i * ((esz - 2) / 2) / 4096);
        if (idx >= esz) idx = esz - 1;
        if (!(idx & 1)) idx--;
        if (idx >= 0 && idx < esz && ew[idx] != 0u) atomicOr(&fe, 1);
        long j = bsz / 2 + ((long)i * (bsz / 2) / 4096);
        if (!(j & 1)) j++;
        if (j < bsz && bw[j] != 0u) atomicOr(&fb, 1);
    }
    __syncthreads();
    if (threadIdx.x == 0) {
        g_is64_edge  = (fe == 0);
        g_is64_batch = (fb == 0);
    }
}

// ---------------- init ------------------------------------------------------
__global__ void k_init() {
    int i = blockIdx.x * blockDim.x + threadIdx.x;
    int st = gridDim.x * blockDim.x;
    for (int j = i; j < NN; j += st) g_deg[j] = 0;
    for (int j = i; j < NG * HO; j += st) g_pool[j] = 0.f;
}

// ---------------- fused convert + degree histogram --------------------------
__global__ void k_prep(const void* __restrict__ ep, const void* __restrict__ bp) {
    int e64 = g_is64_edge, b64 = g_is64_batch;
    long stride = (long)gridDim.x * blockDim.x;
    long i0 = (long)blockIdx.x * blockDim.x + threadIdx.x;
    if (e64) {
        const long long* p = (const long long*)ep;
        for (long i = i0; i < NE; i += stride) {
            int s = (int)p[i];
            int d = (int)p[NE + i];
            g_src[i] = s;
            g_dst[i] = d;
            atomicAdd(&g_deg[d], 1);
        }
    } else {
        const int* p = (const int*)ep;
        for (long i = i0; i < NE; i += stride) {
            int s = p[i];
            int d = p[NE + i];
            g_src[i] = s;
            g_dst[i] = d;
            atomicAdd(&g_deg[d], 1);
        }
    }
    if (b64) {
        const long long* p = (const long long*)bp;
        for (long i = i0; i < NN; i += stride) g_batch[i] = (int)p[i];
    } else {
        const int* p = (const int*)bp;
        for (long i = i0; i < NN; i += stride) g_batch[i] = p[i];
    }
}

// ---------------- scan (block-sum reduce, serial offset, block scan) ---------
__global__ void k_reduce() {
    __shared__ int s[1024];
    int i = blockIdx.x * 1024 + threadIdx.x;
    s[threadIdx.x] = (i < NN) ? g_deg[i] : 0;
    __syncthreads();
    for (int o = 512; o > 0; o >>= 1) {
        if (threadIdx.x < o) s[threadIdx.x] += s[threadIdx.x + o];
        __syncthreads();
    }
    if (threadIdx.x == 0) g_bsum[blockIdx.x] = s[0];
}

__global__ void k_scanoff() {
    const int nb = (NN + 1023) / 1024;
    int run = 0;
    for (int b = 0; b < nb; b++) {
        int t = g_bsum[b];
        g_bsum[b] = run;
        run += t;
    }
}

__global__ void k_scanwrite() {
    __shared__ int s[1024];
    int t = threadIdx.x;
    int i = blockIdx.x * 1024 + t;
    int v = (i < NN) ? g_deg[i] : 0;
    s[t] = v;
    __syncthreads();
    for (int o = 1; o < 1024; o <<= 1) {
        int add = (t >= o) ? s[t - o] : 0;
        __syncthreads();
        if (t >= o) s[t] += add;
        __syncthreads();
    }
    if (i < NN) {
        int excl = s[t] - v + g_bsum[blockIdx.x];
        g_rowptr[i] = excl;
        g_cursor[i] = excl;
        g_dis[i] = rsqrtf((float)(v + 1));  // +1 for the self loop
    }
    if (i == 0) g_rowptr[NN] = NE;
}

__global__ void k_fill() {
    long i0 = (long)blockIdx.x * blockDim.x + threadIdx.x;
    long st = (long)gridDim.x * blockDim.x;
    for (long e = i0; e < NE; e += st) {
        int d = g_dst[e];
        int p = atomicAdd(&g_cursor[d], 1);
        g_col[p] = g_src[e];
    }
}

// ---------------- fold lin1 into conv1: W12 = lin1_w @ conv1_w --------------
__global__ void k_fold(const float* __restrict__ l1w, const float* __restrict__ l1b,
                       const float* __restrict__ c1w) {
    int idx = blockIdx.x * blockDim.x + threadIdx.x;
    if (idx < DD * HH) {
        int k = idx / HH, m = idx % HH;
        float s = 0.f;
        for (int j = 0; j < DD; j++) s += l1w[k * DD + j] * c1w[j * HH + m];
        g_W12[idx] = s;
    } else if (idx < DD * HH + HH) {
        int m = idx - DD * HH;
        float s = 0.f;
        for (int j = 0; j < DD; j++) s += l1b[j] * c1w[j * HH + m];
        g_b12[m] = s;
    }
}

// ---------------- f32x2 GEMM: out[n][MOUT] = (A[n][128] @ W (+bias)) * dis[n]
// MODE 1: A = param x,  W = g_W12,  bias = g_b12,  out = g_h2 (prescaled)
// MODE 2: A = g_h3,     W = param,  bias = none,   out = g_h4 (prescaled)
template <int MOUT, int MODE>
__global__ void __launch_bounds__(256) k_gemm(const float* __restrict__ Aparam,
                                              const float* __restrict__ Wparam) {
    constexpr int KC = 32;
    constexpr int NCG = MOUT / 8;     // threads across cols (8 cols each)
    constexpr int NRG = 256 / NCG;    // thread groups across rows (4 rows each)
    constexpr int ROWS = NRG * 4;     // rows per block
    __shared__ float Xs[ROWS][KC + 1];
    __shared__ float Ws[KC][MOUT];

    const float* A = (MODE == 1) ? Aparam : (const float*)g_h3;
    const float* W = (MODE == 1) ? (const float*)g_W12 : Wparam;
    float* out = (MODE == 1) ? g_h2 : g_h4;

    int tid = threadIdx.x;
    int cg = tid % NCG, rg = tid / NCG;
    int row0 = blockIdx.x * ROWS;

    unsigned long long acc2[4][4];  // 4 rows x 4 col-pairs
#pragma unroll
    for (int r = 0; r < 4; r++)
#pragma unroll
        for (int c = 0; c < 4; c++) acc2[r][c] = 0ull;

    for (int k0 = 0; k0 < DD; k0 += KC) {
#pragma unroll
        for (int idx = tid; idx < ROWS * KC / 4; idx += 256) {
            int r = idx / (KC / 4), j = idx % (KC / 4);
            int gr = row0 + r;
            float4 v = make_float4(0.f, 0.f, 0.f, 0.f);
            if (gr < NN) v = *(const float4*)&A[(size_t)gr * DD + k0 + j * 4];
            Xs[r][j * 4 + 0] = v.x;
            Xs[r][j * 4 + 1] = v.y;
            Xs[r][j * 4 + 2] = v.z;
            Xs[r][j * 4 + 3] = v.w;
        }
#pragma unroll
        for (int idx = tid; idx < KC * MOUT / 4; idx += 256) {
            int kk = idx / (MOUT / 4), j = idx % (MOUT / 4);
            *(float4*)&Ws[kk][j * 4] = *(const float4*)&W[(size_t)(k0 + kk) * MOUT + j * 4];
        }
        __syncthreads();
#pragma unroll
        for (int k = 0; k < KC; k++) {
            unsigned long long aa[4];
#pragma unroll
            for (int r = 0; r < 4; r++) aa[r] = pack2(Xs[rg * 4 + r][k]);
            ulonglong2 q0 = *(ulonglong2*)&Ws[k][cg * 8];
            ulonglong2 q1 = *(ulonglong2*)&Ws[k][cg * 8 + 4];
            unsigned long long bb[4] = {q0.x, q0.y, q1.x, q1.y};
#pragma unroll
            for (int r = 0; r < 4; r++)
#pragma unroll
                for (int c = 0; c < 4; c++) fma2(acc2[r][c], aa[r], bb[c]);
        }
        __syncthreads();
    }

    float bv[8];
#pragma unroll
    for (int c = 0; c < 8; c++) bv[c] = (MODE == 1) ? g_b12[cg * 8 + c] : 0.f;
#pragma unroll
    for (int r = 0; r < 4; r++) {
        int row = row0 + rg * 4 + r;
        if (row < NN) {
            float di = g_dis[row];
            float o[8];
#pragma unroll
            for (int c = 0; c < 4; c++) unpack2(acc2[r][c], o[2 * c], o[2 * c + 1]);
#pragma unroll
            for (int c = 0; c < 8; c++) o[c] = (o[c] + bv[c]) * di;
            *(float4*)&out[(size_t)row * MOUT + cg * 8] =
                make_float4(o[0], o[1], o[2], o[3]);
            *(float4*)&out[(size_t)row * MOUT + cg * 8 + 4] =
                make_float4(o[4], o[5], o[6], o[7]);
        }
    }
}

// ---------------- aggregation 1 (gather-sum, 128 feats) + bias/drop/relu ----
__global__ void k_agg1(const float* __restrict__ c1b, const float* __restrict__ du) {
    int node = (blockIdx.x * blockDim.x + threadIdx.x) >> 5;
    int lane = threadIdx.x & 31;
    if (node >= NN) return;
    float di = g_dis[node];
    size_t base = (size_t)node * HH + lane * 4;
    float4 acc = *(const float4*)&g_h2[base];  // self loop: di * h2s[node] later
    int b = g_rowptr[node], e = g_rowptr[node + 1];
    int t = b;
    for (; t + 4 <= e; t += 4) {
        int s0 = g_col[t], s1 = g_col[t + 1], s2 = g_col[t + 2], s3 = g_col[t + 3];
        float4 u0 = *(const float4*)&g_h2[(size_t)s0 * HH + lane * 4];
        float4 u1 = *(const float4*)&g_h2[(size_t)s1 * HH + lane * 4];
        float4 u2 = *(const float4*)&g_h2[(size_t)s2 * HH + lane * 4];
        float4 u3 = *(const float4*)&g_h2[(size_t)s3 * HH + lane * 4];
        acc.x += (u0.x + u1.x) + (u2.x + u3.x);
        acc.y += (u0.y + u1.y) + (u2.y + u3.y);
        acc.z += (u0.z + u1.z) + (u2.z + u3.z);
        acc.w += (u0.w + u1.w) + (u2.w + u3.w);
    }
    for (; t < e; t++) {
        int s = g_col[t];
        float4 u = *(const float4*)&g_h2[(size_t)s * HH + lane * 4];
        acc.x += u.x; acc.y += u.y; acc.z += u.z; acc.w += u.w;
    }
    int c0 = lane * 4;
    float4 bb = *(const float4*)&c1b[c0];
    float4 dd = *(const float4*)&du[(size_t)node * DD + c0];
    float o[4] = {di * acc.x + bb.x, di * acc.y + bb.y,
                  di * acc.z + bb.z, di * acc.w + bb.w};
    float d4[4] = {dd.x, dd.y, dd.z, dd.w};
#pragma unroll
    for (int q = 0; q < 4; q++) {
        float val = (d4[q] >= 0.5f) ? o[q] * 2.f : 0.f;
        o[q] = fmaxf(val, 0.f);
    }
    *(float4*)&g_h3[base] = make_float4(o[0], o[1], o[2], o[3]);
}

// ---------------- aggregation 2 (64 feats) + bias + fused mean-pool sums ----
// Each warp processes 8 consecutive nodes; since batch is sorted, it carries a
// running per-graph sum and flushes with atomics only on graph change (~8x
// fewer pool atomics).
#define NPW 8
__global__ void k_agg2(const float* __restrict__ c2b) {
    int w = (blockIdx.x * blockDim.x + threadIdx.x) >> 5;
    int lane = threadIdx.x & 31;
    int n0 = w * NPW;
    if (n0 >= NN) return;
    int n1 = min(n0 + NPW, NN);
    int c0 = lane * 2;
    float b0 = c2b[c0], b1 = c2b[c0 + 1];
    int curg = -1;
    float s0 = 0.f, s1 = 0.f;
    for (int node = n0; node < n1; node++) {
        float di = g_dis[node];
        size_t base = (size_t)node * HO + c0;
        float2 v = *(const float2*)&g_h4[base];
        float a0 = v.x, a1 = v.y;
        int b = g_rowptr[node], e = g_rowptr[node + 1];
        int t = b;
        for (; t + 4 <= e; t += 4) {
            int x0 = g_col[t], x1 = g_col[t + 1], x2 = g_col[t + 2], x3 = g_col[t + 3];
            float2 u0 = *(const float2*)&g_h4[(size_t)x0 * HO + c0];
            float2 u1 = *(const float2*)&g_h4[(size_t)x1 * HO + c0];
            float2 u2 = *(const float2*)&g_h4[(size_t)x2 * HO + c0];
            float2 u3 = *(const float2*)&g_h4[(size_t)x3 * HO + c0];
            a0 += (u0.x + u1.x) + (u2.x + u3.x);
            a1 += (u0.y + u1.y) + (u2.y + u3.y);
        }
        for (; t < e; t++) {
            int s = g_col[t];
            float2 u = *(const float2*)&g_h4[(size_t)s * HO + c0];
            a0 += u.x; a1 += u.y;
        }
        float v0 = di * a0 + b0;
        float v1 = di * a1 + b1;
        int g = g_batch[node];
        if (g != curg) {
            if (curg >= 0) {
                atomicAdd(&g_pool[curg * HO + c0], s0);
                atomicAdd(&g_pool[curg * HO + c0 + 1], s1);
            }
            curg = g;
            s0 = 0.f; s1 = 0.f;
        }
        s0 += v0; s1 += v1;
    }
    if (curg >= 0) {
        atomicAdd(&g_pool[curg * HO + c0], s0);
        atomicAdd(&g_pool[curg * HO + c0 + 1], s1);
    }
}

// ---------------- final: (pool / cnt) @ lin2_w + lin2_b ---------------------
// cnt[g] computed by binary search over sorted g_batch (no atomics).
__device__ __forceinline__ int d_lower_bound(int g) {
    int lo = 0, hi = NN;
    while (lo < hi) {
        int m = (lo + hi) >> 1;
        if (g_batch[m] < g) lo = m + 1; else hi = m;
    }
    return lo;
}

__global__ void k_final(const float* __restrict__ w2, const float* __restrict__ b2,
                        float* __restrict__ out) {
    int idx = blockIdx.x * blockDim.x + threadIdx.x;
    if (idx >= NG * NCLS) return;
    int g = idx / NCLS, c = idx % NCLS;
    int cnt = d_lower_bound(g + 1) - d_lower_bound(g);
    float cf = (float)cnt;
    if (cf < 1.f) cf = 1.f;
    float inv = 1.f / cf;
    float s = 0.f;
    for (int j = 0; j < HO; j++) s += g_pool[g * HO + j] * inv * w2[j * NCLS + c];
    out[idx] = s + b2[c];
}

// ---------------- host launcher --------------------------------------------
extern "C" void kernel_launch(void* const* d_in, const int* in_sizes, int n_in,
                              void* d_out, int out_size) {
    const float* x = (const float*)d_in[0];
    const void* edge = d_in[1];
    const void* batch = d_in[2];
    int off = (n_in >= 13 && in_sizes[3] == 1) ? 1 : 0;
    const float* drop_u = (const float*)d_in[3 + off];
    const float* l1w = (const float*)d_in[4 + off];
    const float* l1b = (const float*)d_in[5 + off];
    const float* c1w = (const float*)d_in[6 + off];
    const float* c1b = (const float*)d_in[7 + off];
    const float* c2w = (const float*)d_in[8 + off];
    const float* c2b = (const float*)d_in[9 + off];
    const float* l2w = (const float*)d_in[10 + off];
    const float* l2b = (const float*)d_in[11 + off];
    float* out = (float*)d_out;
    long esz = in_sizes[1];
    long bsz = in_sizes[2];

    k_detect<<<1, 256>>>((const unsigned int*)edge, esz, (const unsigned int*)batch, bsz);
    k_init<<<256, 256>>>();
    k_prep<<<2048, 256>>>(edge, batch);
    k_reduce<<<(NN + 1023) / 1024, 1024>>>();
    k_scanoff<<<1, 1>>>();
    k_scanwrite<<<(NN + 1023) / 1024, 1024>>>();
    k_fill<<<2048, 256>>>();
    k_fold<<<(DD * HH + HH + 255) / 256, 256>>>(l1w, l1b, c1w);
    k_gemm<HH, 1><<<(NN + 63) / 64, 256>>>(x, nullptr);
    k_agg1<<<(NN + 7) / 8, 256>>>(c1b, drop_u);
    k_gemm<HO, 2><<<(NN + 127) / 128, 256>>>(nullptr, c2w);
    {
        int warps = (NN + NPW - 1) / NPW;
        int blocks = (warps + 7) / 8;
        k_agg2<<<blocks, 256>>>(c2b);
    }
    k_final<<<(NG * NCLS + 255) / 256, 256>>>(l2w, l2b, out);
    (void)out_size;
}

// round 5
// speedup vs baseline: 1.4492x; 1.0691x over previous
#include <cuda_runtime.h>
#include <cuda_fp16.h>
#include <math.h>

#define NN 100000
#define NE 1600000
#define DD 128
#define HH 128
#define HO 64
#define NCLS 10
#define NG 128

// ---------------- device scratch (static, no runtime alloc) ----------------
__device__ int    g_is64_edge;
__device__ int    g_is64_batch;
__device__ int    g_col[NE];
__device__ int    g_batch[NN];
__device__ int    g_deg[NN];
__device__ float  g_dis[NN];
__device__ int    g_rowptr[NN];
__device__ int    g_cursor[NN];
__device__ int    g_base_ctr;
__device__ float  g_W12[DD * HH];
__device__ float  g_b12[HH];
__device__ __half g_h2[(size_t)NN * HH];  // (x@W12 + b12) * dis[row]  (prescaled, fp16)
__device__ float  g_h3[(size_t)NN * HH];  // after agg1 + bias + dropout + relu
__device__ __half g_h4[(size_t)NN * HO];  // (h3@conv2_w) * dis[row]   (prescaled, fp16)
__device__ float  g_pool[NG * HO];

// ---------------- f32x2 helpers (FFMA2 on sm_103a) --------------------------
__device__ __forceinline__ unsigned long long pack2(float a) {
    unsigned long long r;
    asm("mov.b64 %0, {%1, %1};" : "=l"(r) : "f"(a));
    return r;
}
__device__ __forceinline__ void fma2(unsigned long long& d, unsigned long long a,
                                     unsigned long long b) {
    asm("fma.rn.f32x2 %0, %1, %2, %0;" : "+l"(d) : "l"(a), "l"(b));
}
__device__ __forceinline__ void unpack2(unsigned long long v, float& lo, float& hi) {
    asm("mov.b64 {%0, %1}, %2;" : "=f"(lo), "=f"(hi) : "l"(v));
}

// ---------------- dtype detection (int64 vs int32 index arrays) ------------
__global__ void k_detect(const unsigned int* __restrict__ ew, long esz,
                         const unsigned int* __restrict__ bw, long bsz) {
    __shared__ int fe, fb;
    if (threadIdx.x == 0) { fe = 0; fb = 0; }
    __syncthreads();
    for (int i = threadIdx.x; i < 4096; i += blockDim.x) {
        long idx = 1 + 2 * ((long)i * ((esz - 2) / 2) / 4096);
        if (idx >= esz) idx = esz - 1;
        if (!(idx & 1)) idx--;
        if (idx >= 0 && idx < esz && ew[idx] != 0u) atomicOr(&fe, 1);
        long j = bsz / 2 + ((long)i * (bsz / 2) / 4096);
        if (!(j & 1)) j++;
        if (j < bsz && bw[j] != 0u) atomicOr(&fb, 1);
    }
    __syncthreads();
    if (threadIdx.x == 0) {
        g_is64_edge  = (fe == 0);
        g_is64_batch = (fb == 0);
    }
}

// ---------------- init ------------------------------------------------------
__global__ void k_init() {
    int i = blockIdx.x * blockDim.x + threadIdx.x;
    int st = gridDim.x * blockDim.x;
    for (int j = i; j < NN; j += st) g_deg[j] = 0;
    for (int j = i; j < NG * HO; j += st) g_pool[j] = 0.f;
    if (i == 0) g_base_ctr = 0;
}

// ---------------- degree histogram (dst read from input) + batch convert ----
__global__ void k_prep(const void* __restrict__ ep, const void* __restrict__ bp) {
    int e64 = g_is64_edge, b64 = g_is64_batch;
    long stride = (long)gridDim.x * blockDim.x;
    long i0 = (long)blockIdx.x * blockDim.x + threadIdx.x;
    if (e64) {
        const long long* p = (const long long*)ep;
        for (long i = i0; i < NE; i += stride) atomicAdd(&g_deg[(int)p[NE + i]], 1);
    } else {
        const int* p = (const int*)ep;
        for (long i = i0; i < NE; i += stride) atomicAdd(&g_deg[p[NE + i]], 1);
    }
    if (b64) {
        const long long* p = (const long long*)bp;
        for (long i = i0; i < NN; i += stride) g_batch[i] = (int)p[i];
    } else {
        const int* p = (const int*)bp;
        for (long i = i0; i < NN; i += stride) g_batch[i] = p[i];
    }
}

// ---------------- single-kernel unordered scan -------------------------------
// Block offsets assigned by arrival order via atomicAdd: CSR segments need not
// be node-ordered since aggregation uses end = rowptr[i] + deg[i].
__global__ void k_scan() {
    __shared__ int s[1024];
    __shared__ int sbase;
    int t = threadIdx.x;
    int i = blockIdx.x * 1024 + t;
    int v = (i < NN) ? g_deg[i] : 0;
    s[t] = v;
    __syncthreads();
    for (int o = 1; o < 1024; o <<= 1) {
        int add = (t >= o) ? s[t - o] : 0;
        __syncthreads();
        if (t >= o) s[t] += add;
        __syncthreads();
    }
    if (t == 1023) sbase = atomicAdd(&g_base_ctr, s[1023]);
    __syncthreads();
    if (i < NN) {
        int excl = s[t] - v + sbase;
        g_rowptr[i] = excl;
        g_cursor[i] = excl;
        g_dis[i] = rsqrtf((float)(v + 1));  // +1 for the self loop
    }
}

// ---------------- CSR fill (src/dst re-decoded from input, hot in L2) --------
__global__ void k_fill(const void* __restrict__ ep) {
    int e64 = g_is64_edge;
    long stride = (long)gridDim.x * blockDim.x;
    long i0 = (long)blockIdx.x * blockDim.x + threadIdx.x;
    if (e64) {
        const long long* p = (const long long*)ep;
        for (long i = i0; i < NE; i += stride) {
            int s = (int)p[i];
            int d = (int)p[NE + i];
            int pos = atomicAdd(&g_cursor[d], 1);
            g_col[pos] = s;
        }
    } else {
        const int* p = (const int*)ep;
        for (long i = i0; i < NE; i += stride) {
            int s = p[i];
            int d = p[NE + i];
            int pos = atomicAdd(&g_cursor[d], 1);
            g_col[pos] = s;
        }
    }
}

// ---------------- fold lin1 into conv1: W12 = lin1_w @ conv1_w --------------
__global__ void k_fold(const float* __restrict__ l1w, const float* __restrict__ l1b,
                       const float* __restrict__ c1w) {
    int idx = blockIdx.x * blockDim.x + threadIdx.x;
    if (idx < DD * HH) {
        int k = idx / HH, m = idx % HH;
        float s = 0.f;
        for (int j = 0; j < DD; j++) s += l1w[k * DD + j] * c1w[j * HH + m];
        g_W12[idx] = s;
    } else if (idx < DD * HH + HH) {
        int m = idx - DD * HH;
        float s = 0.f;
        for (int j = 0; j < DD; j++) s += l1b[j] * c1w[j * HH + m];
        g_b12[m] = s;
    }
}

// ---------------- f32x2 GEMM: out[n][MOUT] = (A[n][128] @ W (+bias)) * dis[n]
// MODE 1: A = param x,  W = g_W12,  bias = g_b12,  out = g_h2 (fp16, prescaled)
// MODE 2: A = g_h3,     W = param,  bias = none,   out = g_h4 (fp16, prescaled)
template <int MOUT, int MODE>
__global__ void __launch_bounds__(256) k_gemm(const float* __restrict__ Aparam,
                                              const float* __restrict__ Wparam) {
    constexpr int KC = 32;
    constexpr int NCG = MOUT / 8;     // threads across cols (8 cols each)
    constexpr int NRG = 256 / NCG;    // thread groups across rows (4 rows each)
    constexpr int ROWS = NRG * 4;     // rows per block
    __shared__ float Xs[ROWS][KC + 1];
    __shared__ float Ws[KC][MOUT];

    const float* A = (MODE == 1) ? Aparam : (const float*)g_h3;
    const float* W = (MODE == 1) ? (const float*)g_W12 : Wparam;
    __half* out = (MODE == 1) ? g_h2 : g_h4;

    int tid = threadIdx.x;
    int cg = tid % NCG, rg = tid / NCG;
    int row0 = blockIdx.x * ROWS;

    unsigned long long acc2[4][4];  // 4 rows x 4 col-pairs
#pragma unroll
    for (int r = 0; r < 4; r++)
#pragma unroll
        for (int c = 0; c < 4; c++) acc2[r][c] = 0ull;

    for (int k0 = 0; k0 < DD; k0 += KC) {
#pragma unroll
        for (int idx = tid; idx < ROWS * KC / 4; idx += 256) {
            int r = idx / (KC / 4), j = idx % (KC / 4);
            int gr = row0 + r;
            float4 v = make_float4(0.f, 0.f, 0.f, 0.f);
            if (gr < NN) v = *(const float4*)&A[(size_t)gr * DD + k0 + j * 4];
            Xs[r][j * 4 + 0] = v.x;
            Xs[r][j * 4 + 1] = v.y;
            Xs[r][j * 4 + 2] = v.z;
            Xs[r][j * 4 + 3] = v.w;
        }
#pragma unroll
        for (int idx = tid; idx < KC * MOUT / 4; idx += 256) {
            int kk = idx / (MOUT / 4), j = idx % (MOUT / 4);
            *(float4*)&Ws[kk][j * 4] = *(const float4*)&W[(size_t)(k0 + kk) * MOUT + j * 4];
        }
        __syncthreads();
#pragma unroll
        for (int k = 0; k < KC; k++) {
            unsigned long long aa[4];
#pragma unroll
            for (int r = 0; r < 4; r++) aa[r] = pack2(Xs[rg * 4 + r][k]);
            ulonglong2 q0 = *(ulonglong2*)&Ws[k][cg * 8];
            ulonglong2 q1 = *(ulonglong2*)&Ws[k][cg * 8 + 4];
            unsigned long long bb[4] = {q0.x, q0.y, q1.x, q1.y};
#pragma unroll
            for (int r = 0; r < 4; r++)
#pragma unroll
                for (int c = 0; c < 4; c++) fma2(acc2[r][c], aa[r], bb[c]);
        }
        __syncthreads();
    }

    float bv[8];
#pragma unroll
    for (int c = 0; c < 8; c++) bv[c] = (MODE == 1) ? g_b12[cg * 8 + c] : 0.f;
#pragma unroll
    for (int r = 0; r < 4; r++) {
        int row = row0 + rg * 4 + r;
        if (row < NN) {
            float di = g_dis[row];
            float o[8];
#pragma unroll
            for (int c = 0; c < 4; c++) unpack2(acc2[r][c], o[2 * c], o[2 * c + 1]);
#pragma unroll
            for (int c = 0; c < 8; c++) o[c] = (o[c] + bv[c]) * di;
            __half2 hh[4];
#pragma unroll
            for (int c = 0; c < 4; c++)
                hh[c] = __floats2half2_rn(o[2 * c], o[2 * c + 1]);
            uint4 pk;
            pk.x = *(unsigned*)&hh[0];
            pk.y = *(unsigned*)&hh[1];
            pk.z = *(unsigned*)&hh[2];
            pk.w = *(unsigned*)&hh[3];
            *(uint4*)&out[(size_t)row * MOUT + cg * 8] = pk;
        }
    }
}

// ---------------- aggregation 1 (gather-sum fp16, 128 feats) + bias/drop/relu
__global__ void k_agg1(const float* __restrict__ c1b, const float* __restrict__ du) {
    int node = (blockIdx.x * blockDim.x + threadIdx.x) >> 5;
    int lane = threadIdx.x & 31;
    if (node >= NN) return;
    float di = g_dis[node];
    size_t base = (size_t)node * HH + lane * 4;
    uint2 rs = *(const uint2*)&g_h2[base];  // self loop term
    float2 f0 = __half22float2(*(__half2*)&rs.x);
    float2 f1 = __half22float2(*(__half2*)&rs.y);
    float ax = f0.x, ay = f0.y, az = f1.x, aw = f1.y;
    int b = g_rowptr[node];
    int e = b + g_deg[node];
    int t = b;
    for (; t + 4 <= e; t += 4) {
        int s0 = g_col[t], s1 = g_col[t + 1], s2 = g_col[t + 2], s3 = g_col[t + 3];
        uint2 r0 = *(const uint2*)&g_h2[(size_t)s0 * HH + lane * 4];
        uint2 r1 = *(const uint2*)&g_h2[(size_t)s1 * HH + lane * 4];
        uint2 r2 = *(const uint2*)&g_h2[(size_t)s2 * HH + lane * 4];
        uint2 r3 = *(const uint2*)&g_h2[(size_t)s3 * HH + lane * 4];
        float2 a0 = __half22float2(*(__half2*)&r0.x), b0 = __half22float2(*(__half2*)&r0.y);
        float2 a1 = __half22float2(*(__half2*)&r1.x), b1 = __half22float2(*(__half2*)&r1.y);
        float2 a2 = __half22float2(*(__half2*)&r2.x), b2 = __half22float2(*(__half2*)&r2.y);
        float2 a3 = __half22float2(*(__half2*)&r3.x), b3 = __half22float2(*(__half2*)&r3.y);
        ax += (a0.x + a1.x) + (a2.x + a3.x);
        ay += (a0.y + a1.y) + (a2.y + a3.y);
        az += (b0.x + b1.x) + (b2.x + b3.x);
        aw += (b0.y + b1.y) + (b2.y + b3.y);
    }
    for (; t < e; t++) {
        int s = g_col[t];
        uint2 r = *(const uint2*)&g_h2[(size_t)s * HH + lane * 4];
        float2 a = __half22float2(*(__half2*)&r.x);
        float2 bq = __half22float2(*(__half2*)&r.y);
        ax += a.x; ay += a.y; az += bq.x; aw += bq.y;
    }
    int c0 = lane * 4;
    float4 bb = *(const float4*)&c1b[c0];
    float4 dd = *(const float4*)&du[(size_t)node * DD + c0];
    float o[4] = {di * ax + bb.x, di * ay + bb.y, di * az + bb.z, di * aw + bb.w};
    float d4[4] = {dd.x, dd.y, dd.z, dd.w};
#pragma unroll
    for (int q = 0; q < 4; q++) {
        float val = (d4[q] >= 0.5f) ? o[q] * 2.f : 0.f;
        o[q] = fmaxf(val, 0.f);
    }
    *(float4*)&g_h3[base] = make_float4(o[0], o[1], o[2], o[3]);
}

// ---------------- aggregation 2 (fp16, 64 feats) + bias + fused mean-pool ----
#define NPW 8
__global__ void k_agg2(const float* __restrict__ c2b) {
    int w = (blockIdx.x * blockDim.x + threadIdx.x) >> 5;
    int lane = threadIdx.x & 31;
    int n0 = w * NPW;
    if (n0 >= NN) return;
    int n1 = min(n0 + NPW, NN);
    int c0 = lane * 2;
    float b0 = c2b[c0], b1 = c2b[c0 + 1];
    int curg = -1;
    float s0 = 0.f, s1 = 0.f;
    for (int node = n0; node < n1; node++) {
        float di = g_dis[node];
        float2 v = __half22float2(*(const __half2*)&g_h4[(size_t)node * HO + c0]);
        float a0 = v.x, a1 = v.y;
        int b = g_rowptr[node];
        int e = b + g_deg[node];
        int t = b;
        for (; t + 4 <= e; t += 4) {
            int x0 = g_col[t], x1 = g_col[t + 1], x2 = g_col[t + 2], x3 = g_col[t + 3];
            float2 u0 = __half22float2(*(const __half2*)&g_h4[(size_t)x0 * HO + c0]);
            float2 u1 = __half22float2(*(const __half2*)&g_h4[(size_t)x1 * HO + c0]);
            float2 u2 = __half22float2(*(const __half2*)&g_h4[(size_t)x2 * HO + c0]);
            float2 u3 = __half22float2(*(const __half2*)&g_h4[(size_t)x3 * HO + c0]);
            a0 += (u0.x + u1.x) + (u2.x + u3.x);
            a1 += (u0.y + u1.y) + (u2.y + u3.y);
        }
        for (; t < e; t++) {
            int s = g_col[t];
            float2 u = __half22float2(*(const __half2*)&g_h4[(size_t)s * HO + c0]);
            a0 += u.x; a1 += u.y;
        }
        float v0 = di * a0 + b0;
        float v1 = di * a1 + b1;
        int g = g_batch[node];
        if (g != curg) {
            if (curg >= 0) {
                atomicAdd(&g_pool[curg * HO + c0], s0);
                atomicAdd(&g_pool[curg * HO + c0 + 1], s1);
            }
            curg = g;
            s0 = 0.f; s1 = 0.f;
        }
        s0 += v0; s1 += v1;
    }
    if (curg >= 0) {
        atomicAdd(&g_pool[curg * HO + c0], s0);
        atomicAdd(&g_pool[curg * HO + c0 + 1], s1);
    }
}

// ---------------- final: (pool / cnt) @ lin2_w + lin2_b ---------------------
__device__ __forceinline__ int d_lower_bound(int g) {
    int lo = 0, hi = NN;
    while (lo < hi) {
        int m = (lo + hi) >> 1;
        if (g_batch[m] < g) lo = m + 1; else hi = m;
    }
    return lo;
}

__global__ void k_final(const float* __restrict__ w2, const float* __restrict__ b2,
                        float* __restrict__ out) {
    int idx = blockIdx.x * blockDim.x + threadIdx.x;
    if (idx >= NG * NCLS) return;
    int g = idx / NCLS, c = idx % NCLS;
    int cnt = d_lower_bound(g + 1) - d_lower_bound(g);
    float cf = (float)cnt;
    if (cf < 1.f) cf = 1.f;
    float inv = 1.f / cf;
    float s = 0.f;
    for (int j = 0; j < HO; j++) s += g_pool[g * HO + j] * inv * w2[j * NCLS + c];
    out[idx] = s + b2[c];
}

// ---------------- host launcher --------------------------------------------
extern "C" void kernel_launch(void* const* d_in, const int* in_sizes, int n_in,
                              void* d_out, int out_size) {
    const float* x = (const float*)d_in[0];
    const void* edge = d_in[1];
    const void* batch = d_in[2];
    int off = (n_in >= 13 && in_sizes[3] == 1) ? 1 : 0;
    const float* drop_u = (const float*)d_in[3 + off];
    const float* l1w = (const float*)d_in[4 + off];
    const float* l1b = (const float*)d_in[5 + off];
    const float* c1w = (const float*)d_in[6 + off];
    const float* c1b = (const float*)d_in[7 + off];
    const float* c2w = (const float*)d_in[8 + off];
    const float* c2b = (const float*)d_in[9 + off];
    const float* l2w = (const float*)d_in[10 + off];
    const float* l2b = (const float*)d_in[11 + off];
    float* out = (float*)d_out;
    long esz = in_sizes[1];
    long bsz = in_sizes[2];

    k_detect<<<1, 256>>>((const unsigned int*)edge, esz, (const unsigned int*)batch, bsz);
    k_init<<<256, 256>>>();
    k_prep<<<2048, 256>>>(edge, batch);
    k_scan<<<(NN + 1023) / 1024, 1024>>>();
    k_fill<<<2048, 256>>>(edge);
    k_fold<<<(DD * HH + HH + 255) / 256, 256>>>(l1w, l1b, c1w);
    k_gemm<HH, 1><<<(NN + 63) / 64, 256>>>(x, nullptr);
    k_agg1<<<(NN + 7) / 8, 256>>>(c1b, drop_u);
    k_gemm<HO, 2><<<(NN + 127) / 128, 256>>>(nullptr, c2w);
    {
        int warps = (NN + NPW - 1) / NPW;
        int blocks = (warps + 7) / 8;
        k_agg2<<<blocks, 256>>>(c2b);
    }
    k_final<<<(NG * NCLS + 255) / 256, 256>>>(l2w, l2b, out);
    (void)out_size;
}

// round 7
// speedup vs baseline: 2.4993x; 1.7245x over previous
#include <cuda_runtime.h>
#include <cuda_fp16.h>
#include <math.h>

#define NN 100000
#define NE 1600000
#define DD 128
#define HH 128
#define HO 64
#define NCLS 10
#define NG 128

// ---------------- device scratch (static, no runtime alloc) ----------------
__device__ int    g_is64_edge;
__device__ int    g_is64_batch;
__device__ int    g_col[NE];
__device__ int    g_batch[NN];
__device__ int    g_deg[NN];
__device__ float  g_dis[NN];
__device__ int    g_rowptr[NN];
__device__ int    g_cursor[NN];
__device__ int    g_base_ctr;
__device__ __half g_W12T[HH * DD];        // (lin1_w @ conv1_w)^T, fp16 n-major
__device__ float  g_b12[HH];
__device__ __half g_W2T[HO * DD];         // conv2_w^T, fp16 n-major
__device__ __half g_h2[(size_t)NN * HH];  // (x@W12 + b12) * dis[row]  (fp16)
__device__ __half g_h3[(size_t)NN * HH];  // after agg1 + bias + dropout + relu (fp16)
__device__ __half g_h4[(size_t)NN * HO];  // (h3@conv2_w) * dis[row]   (fp16)
__device__ float  g_pool[NG * HO];

// ---------------- warp mma helper -------------------------------------------
__device__ __forceinline__ void mma16816(float* c, const unsigned* a, const unsigned* b) {
    asm volatile(
        "mma.sync.aligned.m16n8k16.row.col.f32.f16.f16.f32 "
        "{%0,%1,%2,%3}, {%4,%5,%6,%7}, {%8,%9}, {%0,%1,%2,%3};"
        : "+f"(c[0]), "+f"(c[1]), "+f"(c[2]), "+f"(c[3])
        : "r"(a[0]), "r"(a[1]), "r"(a[2]), "r"(a[3]), "r"(b[0]), "r"(b[1]));
}

// ---------------- dtype detect (block 0) + init (all blocks) -----------------
__global__ void k_detect_init(const unsigned int* __restrict__ ew, long esz,
                              const unsigned int* __restrict__ bw, long bsz) {
    if (blockIdx.x == 0) {
        __shared__ int fe, fb;
        if (threadIdx.x == 0) { fe = 0; fb = 0; }
        __syncthreads();
        for (int i = threadIdx.x; i < 4096; i += blockDim.x) {
            long idx = 1 + 2 * ((long)i * ((esz - 2) / 2) / 4096);
            if (idx >= esz) idx = esz - 1;
            if (!(idx & 1)) idx--;
            if (idx >= 0 && idx < esz && ew[idx] != 0u) atomicOr(&fe, 1);
            long j = bsz / 2 + ((long)i * (bsz / 2) / 4096);
            if (!(j & 1)) j++;
            if (j < bsz && bw[j] != 0u) atomicOr(&fb, 1);
        }
        __syncthreads();
        if (threadIdx.x == 0) {
            g_is64_edge  = (fe == 0);
            g_is64_batch = (fb == 0);
            g_base_ctr = 0;
        }
    }
    int i = blockIdx.x * blockDim.x + threadIdx.x;
    int st = gridDim.x * blockDim.x;
    for (int j = i; j < NN; j += st) g_deg[j] = 0;
    for (int j = i; j < NG * HO; j += st) g_pool[j] = 0.f;
}

// ---------------- degree histogram (dst read from input) + batch convert ----
__global__ void k_prep(const void* __restrict__ ep, const void* __restrict__ bp) {
    int e64 = g_is64_edge, b64 = g_is64_batch;
    long stride = (long)gridDim.x * blockDim.x;
    long i0 = (long)blockIdx.x * blockDim.x + threadIdx.x;
    if (e64) {
        const long long* p = (const long long*)ep;
        for (long i = i0; i < NE; i += stride) atomicAdd(&g_deg[(int)p[NE + i]], 1);
    } else {
        const int* p = (const int*)ep;
        for (long i = i0; i < NE; i += stride) atomicAdd(&g_deg[p[NE + i]], 1);
    }
    if (b64) {
        const long long* p = (const long long*)bp;
        for (long i = i0; i < NN; i += stride) g_batch[i] = (int)p[i];
    } else {
        const int* p = (const int*)bp;
        for (long i = i0; i < NN; i += stride) g_batch[i] = p[i];
    }
}

// ---------------- single-kernel unordered scan -------------------------------
__global__ void k_scan() {
    __shared__ int s[1024];
    __shared__ int sbase;
    int t = threadIdx.x;
    int i = blockIdx.x * 1024 + t;
    int v = (i < NN) ? g_deg[i] : 0;
    s[t] = v;
    __syncthreads();
    for (int o = 1; o < 1024; o <<= 1) {
        int add = (t >= o) ? s[t - o] : 0;
        __syncthreads();
        if (t >= o) s[t] += add;
        __syncthreads();
    }
    if (t == 1023) sbase = atomicAdd(&g_base_ctr, s[1023]);
    __syncthreads();
    if (i < NN) {
        int excl = s[t] - v + sbase;
        g_rowptr[i] = excl;
        g_cursor[i] = excl;
        g_dis[i] = rsqrtf((float)(v + 1));  // +1 for the self loop
    }
}

// ---------------- CSR fill ----------------------------------------------------
__global__ void k_fill(const void* __restrict__ ep) {
    int e64 = g_is64_edge;
    long stride = (long)gridDim.x * blockDim.x;
    long i0 = (long)blockIdx.x * blockDim.x + threadIdx.x;
    if (e64) {
        const long long* p = (const long long*)ep;
        for (long i = i0; i < NE; i += stride) {
            int s = (int)p[i];
            int d = (int)p[NE + i];
            int pos = atomicAdd(&g_cursor[d], 1);
            g_col[pos] = s;
        }
    } else {
        const int* p = (const int*)ep;
        for (long i = i0; i < NE; i += stride) {
            int s = p[i];
            int d = p[NE + i];
            int pos = atomicAdd(&g_cursor[d], 1);
            g_col[pos] = s;
        }
    }
}

// ---------------- fold lin1 into conv1 + transpose weights to fp16 ----------
// g_W12T[n][k] = (lin1_w @ conv1_w)[k][n];  g_b12 = lin1_b @ conv1_w;
// g_W2T[n][k]  = conv2_w[k][n]
__global__ void k_fold(const float* __restrict__ l1w, const float* __restrict__ l1b,
                       const float* __restrict__ c1w, const float* __restrict__ c2w) {
    int idx = blockIdx.x * blockDim.x + threadIdx.x;
    if (idx < DD * HH) {
        int k = idx / HH, m = idx % HH;
        float s = 0.f;
        for (int j = 0; j < DD; j++) s += l1w[k * DD + j] * c1w[j * HH + m];
        g_W12T[m * DD + k] = __float2half(s);
    } else if (idx < DD * HH + HH) {
        int m = idx - DD * HH;
        float s = 0.f;
        for (int j = 0; j < DD; j++) s += l1b[j] * c1w[j * HH + m];
        g_b12[m] = s;
    } else if (idx < DD * HH + HH + HH * HO) {
        int j = idx - (DD * HH + HH);
        int k = j / HO, n = j % HO;
        g_W2T[n * DD + k] = __float2half(c2w[k * HO + n]);
    }
}

// ---------------- HMMA GEMM: out[n][MOUT] = (A[n][128] @ W (+bias)) * dis[n]
// MODE 1: A = x (fp32), W = g_W12T, bias = g_b12, out = g_h2
// MODE 2: A = g_h3 (fp16), W = g_W2T, no bias,    out = g_h4
template <int MOUT, int MODE>
__global__ void __launch_bounds__(256) k_gemm(const float* __restrict__ x) {
    constexpr int ROWS = 64;
    constexpr int KPAD = 72;                 // 64 + 8 halves pad -> conflict-free
    constexpr int NW = MOUT / 4;             // warp n-width (32 or 16)
    constexpr int NT = NW / 8;               // n8-tiles per warp (4 or 2)
    __shared__ __half As[ROWS][KPAD];
    __shared__ __half Ws[MOUT][KPAD];

    int tid = threadIdx.x;
    int wid = tid >> 5, lane = tid & 31;
    int gid = lane >> 2, tg = lane & 3;
    int wm = wid >> 2, wn = wid & 3;         // 2 x 4 warp grid
    int row0 = blockIdx.x * ROWS;
    __half* out = (MODE == 1) ? g_h2 : g_h4;
    const __half* WT = (MODE == 1) ? g_W12T : g_W2T;

    float acc[2][NT][4];
#pragma unroll
    for (int mt = 0; mt < 2; mt++)
#pragma unroll
        for (int nt = 0; nt < NT; nt++)
#pragma unroll
            for (int q = 0; q < 4; q++) acc[mt][nt][q] = 0.f;

#pragma unroll
    for (int ch = 0; ch < 2; ch++) {
        int k0 = ch * 64;
        // ---- load A chunk into smem (fp16) ----
        if (MODE == 1) {
#pragma unroll
            for (int idx = tid; idx < ROWS * 16; idx += 256) {
                int r = idx >> 4, q = idx & 15;
                int gr = row0 + r;
                float4 v = make_float4(0.f, 0.f, 0.f, 0.f);
                if (gr < NN) v = *(const float4*)&x[(size_t)gr * DD + k0 + q * 4];
                *(__half2*)&As[r][q * 4]     = __floats2half2_rn(v.x, v.y);
                *(__half2*)&As[r][q * 4 + 2] = __floats2half2_rn(v.z, v.w);
            }
        } else {
#pragma unroll
            for (int idx = tid; idx < ROWS * 8; idx += 256) {
                int r = idx >> 3, q = idx & 7;
                int gr = row0 + r;
                uint4 v = make_uint4(0u, 0u, 0u, 0u);
                if (gr < NN) v = *(const uint4*)&g_h3[(size_t)gr * HH + k0 + q * 8];
                *(uint4*)&As[r][q * 8] = v;
            }
        }
        // ---- load W^T chunk (already fp16 n-major) ----
#pragma unroll
        for (int idx = tid; idx < MOUT * 8; idx += 256) {
            int n = idx >> 3, q = idx & 7;
            *(uint4*)&Ws[n][q * 8] = *(const uint4*)&WT[n * DD + k0 + q * 8];
        }
        __syncthreads();
        // ---- 4 k16 steps ----
#pragma unroll
        for (int ks = 0; ks < 4; ks++) {
            int kk = ks * 16;
            unsigned af[2][4];
#pragma unroll
            for (int mt = 0; mt < 2; mt++) {
                int r = wm * 32 + mt * 16 + gid;
                af[mt][0] = *(unsigned*)&As[r][kk + tg * 2];
                af[mt][1] = *(unsigned*)&As[r + 8][kk + tg * 2];
                af[mt][2] = *(unsigned*)&As[r][kk + tg * 2 + 8];
                af[mt][3] = *(unsigned*)&As[r + 8][kk + tg * 2 + 8];
            }
            unsigned bf[NT][2];
#pragma unroll
            for (int nt = 0; nt < NT; nt++) {
                int n = wn * NW + nt * 8 + gid;
                bf[nt][0] = *(unsigned*)&Ws[n][kk + tg * 2];
                bf[nt][1] = *(unsigned*)&Ws[n][kk + tg * 2 + 8];
            }
#pragma unroll
            for (int mt = 0; mt < 2; mt++)
#pragma unroll
                for (int nt = 0; nt < NT; nt++)
                    mma16816(acc[mt][nt], af[mt], bf[nt]);
        }
        __syncthreads();
    }

    // ---- epilogue: +bias, *dis, fp16 store ----
#pragma unroll
    for (int mt = 0; mt < 2; mt++) {
        int r_lo = row0 + wm * 32 + mt * 16 + gid;
        int r_hi = r_lo + 8;
        float dlo = (r_lo < NN) ? g_dis[r_lo] : 0.f;
        float dhi = (r_hi < NN) ? g_dis[r_hi] : 0.f;
#pragma unroll
        for (int nt = 0; nt < NT; nt++) {
            int n = wn * NW + nt * 8 + tg * 2;
            float b0 = 0.f, b1 = 0.f;
            if (MODE == 1) { b0 = g_b12[n]; b1 = g_b12[n + 1]; }
            if (r_lo < NN)
                *(__half2*)&out[(size_t)r_lo * MOUT + n] =
                    __floats2half2_rn((acc[mt][nt][0] + b0) * dlo,
                                      (acc[mt][nt][1] + b1) * dlo);
            if (r_hi < NN)
                *(__half2*)&out[(size_t)r_hi * MOUT + n] =
                    __floats2half2_rn((acc[mt][nt][2] + b0) * dhi,
                                      (acc[mt][nt][3] + b1) * dhi);
        }
    }
}

// ---------------- aggregation 1 (gather-sum fp16, 128 feats) + bias/drop/relu
__global__ void k_agg1(const float* __restrict__ c1b, const float* __restrict__ du) {
    int node = (blockIdx.x * blockDim.x + threadIdx.x) >> 5;
    int lane = threadIdx.x & 31;
    if (node >= NN) return;
    float di = g_dis[node];
    size_t base = (size_t)node * HH + lane * 4;
    uint2 rs = *(const uint2*)&g_h2[base];  // self loop term
    float2 f0 = __half22float2(*(__half2*)&rs.x);
    float2 f1 = __half22float2(*(__half2*)&rs.y);
    float ax = f0.x, ay = f0.y, az = f1.x, aw = f1.y;
    int b = g_rowptr[node];
    int e = b + g_deg[node];
    int t = b;
    for (; t + 4 <= e; t += 4) {
        int s0 = g_col[t], s1 = g_col[t + 1], s2 = g_col[t + 2], s3 = g_col[t + 3];
        uint2 r0 = *(const uint2*)&g_h2[(size_t)s0 * HH + lane * 4];
        uint2 r1 = *(const uint2*)&g_h2[(size_t)s1 * HH + lane * 4];
        uint2 r2 = *(const uint2*)&g_h2[(size_t)s2 * HH + lane * 4];
        uint2 r3 = *(const uint2*)&g_h2[(size_t)s3 * HH + lane * 4];
        float2 a0 = __half22float2(*(__half2*)&r0.x), b0 = __half22float2(*(__half2*)&r0.y);
        float2 a1 = __half22float2(*(__half2*)&r1.x), b1 = __half22float2(*(__half2*)&r1.y);
        float2 a2 = __half22float2(*(__half2*)&r2.x), b2 = __half22float2(*(__half2*)&r2.y);
        float2 a3 = __half22float2(*(__half2*)&r3.x), b3 = __half22float2(*(__half2*)&r3.y);
        ax += (a0.x + a1.x) + (a2.x + a3.x);
        ay += (a0.y + a1.y) + (a2.y + a3.y);
        az += (b0.x + b1.x) + (b2.x + b3.x);
        aw += (b0.y + b1.y) + (b2.y + b3.y);
    }
    for (; t < e; t++) {
        int s = g_col[t];
        uint2 r = *(const uint2*)&g_h2[(size_t)s * HH + lane * 4];
        float2 a = __half22float2(*(__half2*)&r.x);
        float2 bq = __half22float2(*(__half2*)&r.y);
        ax += a.x; ay += a.y; az += bq.x; aw += bq.y;
    }
    int c0 = lane * 4;
    float4 bb = *(const float4*)&c1b[c0];
    float4 dd = *(const float4*)&du[(size_t)node * DD + c0];
    float o[4] = {di * ax + bb.x, di * ay + bb.y, di * az + bb.z, di * aw + bb.w};
    float d4[4] = {dd.x, dd.y, dd.z, dd.w};
#pragma unroll
    for (int q = 0; q < 4; q++) {
        float val = (d4[q] >= 0.5f) ? o[q] * 2.f : 0.f;
        o[q] = fmaxf(val, 0.f);
    }
    uint2 pk;
    __half2 h0 = __floats2half2_rn(o[0], o[1]);
    __half2 h1 = __floats2half2_rn(o[2], o[3]);
    pk.x = *(unsigned*)&h0;
    pk.y = *(unsigned*)&h1;
    *(uint2*)&g_h3[base] = pk;
}

// ---------------- aggregation 2 (fp16, 64 feats) + bias + fused mean-pool ----
#define NPW 8
__global__ void k_agg2(const float* __restrict__ c2b) {
    int w = (blockIdx.x * blockDim.x + threadIdx.x) >> 5;
    int lane = threadIdx.x & 31;
    int n0 = w * NPW;
    if (n0 >= NN) return;
    int n1 = min(n0 + NPW, NN);
    int c0 = lane * 2;
    float b0 = c2b[c0], b1 = c2b[c0 + 1];
    int curg = -1;
    float s0 = 0.f, s1 = 0.f;
    for (int node = n0; node < n1; node++) {
        float di = g_dis[node];
        float2 v = __half22float2(*(const __half2*)&g_h4[(size_t)node * HO + c0]);
        float a0 = v.x, a1 = v.y;
        int b = g_rowptr[node];
        int e = b + g_deg[node];
        int t = b;
        for (; t + 4 <= e; t += 4) {
            int x0 = g_col[t], x1 = g_col[t + 1], x2 = g_col[t + 2], x3 = g_col[t + 3];
            float2 u0 = __half22float2(*(const __half2*)&g_h4[(size_t)x0 * HO + c0]);
            float2 u1 = __half22float2(*(const __half2*)&g_h4[(size_t)x1 * HO + c0]);
            float2 u2 = __half22float2(*(const __half2*)&g_h4[(size_t)x2 * HO + c0]);
            float2 u3 = __half22float2(*(const __half2*)&g_h4[(size_t)x3 * HO + c0]);
            a0 += (u0.x + u1.x) + (u2.x + u3.x);
            a1 += (u0.y + u1.y) + (u2.y + u3.y);
        }
        for (; t < e; t++) {
            int s = g_col[t];
            float2 u = __half22float2(*(const __half2*)&g_h4[(size_t)s * HO + c0]);
            a0 += u.x; a1 += u.y;
        }
        float v0 = di * a0 + b0;
        float v1 = di * a1 + b1;
        int g = g_batch[node];
        if (g != curg) {
            if (curg >= 0) {
                atomicAdd(&g_pool[curg * HO + c0], s0);
                atomicAdd(&g_pool[curg * HO + c0 + 1], s1);
            }
            curg = g;
            s0 = 0.f; s1 = 0.f;
        }
        s0 += v0; s1 += v1;
    }
    if (curg >= 0) {
        atomicAdd(&g_pool[curg * HO + c0], s0);
        atomicAdd(&g_pool[curg * HO + c0 + 1], s1);
    }
}

// ---------------- final: (pool / cnt) @ lin2_w + lin2_b ---------------------
__device__ __forceinline__ int d_lower_bound(int g) {
    int lo = 0, hi = NN;
    while (lo < hi) {
        int m = (lo + hi) >> 1;
        if (g_batch[m] < g) lo = m + 1; else hi = m;
    }
    return lo;
}

__global__ void k_final(const float* __restrict__ w2, const float* __restrict__ b2,
                        float* __restrict__ out) {
    int idx = blockIdx.x * blockDim.x + threadIdx.x;
    if (idx >= NG * NCLS) return;
    int g = idx / NCLS, c = idx % NCLS;
    int cnt = d_lower_bound(g + 1) - d_lower_bound(g);
    float cf = (float)cnt;
    if (cf < 1.f) cf = 1.f;
    float inv = 1.f / cf;
    float s = 0.f;
    for (int j = 0; j < HO; j++) s += g_pool[g * HO + j] * inv * w2[j * NCLS + c];
    out[idx] = s + b2[c];
}

// ---------------- host launcher --------------------------------------------
extern "C" void kernel_launch(void* const* d_in, const int* in_sizes, int n_in,
                              void* d_out, int out_size) {
    const float* x = (const float*)d_in[0];
    const void* edge = d_in[1];
    const void* batch = d_in[2];
    int off = (n_in >= 13 && in_sizes[3] == 1) ? 1 : 0;
    const float* drop_u = (const float*)d_in[3 + off];
    const float* l1w = (const float*)d_in[4 + off];
    const float* l1b = (const float*)d_in[5 + off];
    const float* c1w = (const float*)d_in[6 + off];
    const float* c1b = (const float*)d_in[7 + off];
    const float* c2w = (const float*)d_in[8 + off];
    const float* c2b = (const float*)d_in[9 + off];
    const float* l2w = (const float*)d_in[10 + off];
    const float* l2b = (const float*)d_in[11 + off];
    float* out = (float*)d_out;
    long esz = in_sizes[1];
    long bsz = in_sizes[2];

    k_detect_init<<<256, 256>>>((const unsigned int*)edge, esz,
                                (const unsigned int*)batch, bsz);
    k_prep<<<2048, 256>>>(edge, batch);
    k_scan<<<(NN + 1023) / 1024, 1024>>>();
    k_fill<<<2048, 256>>>(edge);
    k_fold<<<(DD * HH + HH + HH * HO + 255) / 256, 256>>>(l1w, l1b, c1w, c2w);
    k_gemm<HH, 1><<<(NN + 63) / 64, 256>>>(x);
    k_agg1<<<(NN + 7) / 8, 256>>>(c1b, drop_u);
    k_gemm<HO, 2><<<(NN + 63) / 64, 256>>>(nullptr);
    {
        int warps = (NN + NPW - 1) / NPW;
        int blocks = (warps + 7) / 8;
        k_agg2<<<blocks, 256>>>(c2b);
    }
    k_final<<<(NG * NCLS + 255) / 256, 256>>>(l2w, l2b, out);
    (void)out_size;
}

// round 8
// speedup vs baseline: 2.5739x; 1.0299x over previous
#include <cuda_runtime.h>
#include <cuda_fp16.h>
#include <math.h>

#define NN 100000
#define NE 1600000
#define DD 128
#define HH 128
#define HO 64
#define NCLS 10
#define NG 128

// ---------------- device scratch (static, no runtime alloc) ----------------
__device__ int    g_is64_edge;
__device__ int    g_is64_batch;
__device__ int    g_col[NE];
__device__ int    g_rank[NE];             // rank of edge within its dst segment
__device__ int    g_batch[NN];
__device__ int    g_deg[NN];
__device__ float  g_dis[NN];
__device__ int    g_rowptr[NN];
__device__ int    g_base_ctr;
__device__ __half g_W12T[HH * DD];        // (lin1_w @ conv1_w)^T, fp16 n-major
__device__ float  g_b12[HH];
__device__ __half g_W2T[HO * DD];         // conv2_w^T, fp16 n-major
__device__ __half g_h2[(size_t)NN * HH];  // (x@W12 + b12) * dis[row]  (fp16)
__device__ __half g_h3[(size_t)NN * HH];  // after agg1 + bias + dropout + relu (fp16)
__device__ __half g_h4[(size_t)NN * HO];  // (h3@conv2_w) * dis[row]   (fp16)
__device__ float  g_pool[NG * HO];

// ---------------- warp mma helper -------------------------------------------
__device__ __forceinline__ void mma16816(float* c, const unsigned* a, const unsigned* b) {
    asm volatile(
        "mma.sync.aligned.m16n8k16.row.col.f32.f16.f16.f32 "
        "{%0,%1,%2,%3}, {%4,%5,%6,%7}, {%8,%9}, {%0,%1,%2,%3};"
        : "+f"(c[0]), "+f"(c[1]), "+f"(c[2]), "+f"(c[3])
        : "r"(a[0]), "r"(a[1]), "r"(a[2]), "r"(a[3]), "r"(b[0]), "r"(b[1]));
}

// ---------------- dtype detect (block 0) + init (all blocks) -----------------
__global__ void k_detect_init(const unsigned int* __restrict__ ew, long esz,
                              const unsigned int* __restrict__ bw, long bsz) {
    if (blockIdx.x == 0) {
        __shared__ int fe, fb;
        if (threadIdx.x == 0) { fe = 0; fb = 0; }
        __syncthreads();
        for (int i = threadIdx.x; i < 4096; i += blockDim.x) {
            long idx = 1 + 2 * ((long)i * ((esz - 2) / 2) / 4096);
            if (idx >= esz) idx = esz - 1;
            if (!(idx & 1)) idx--;
            if (idx >= 0 && idx < esz && ew[idx] != 0u) atomicOr(&fe, 1);
            long j = bsz / 2 + ((long)i * (bsz / 2) / 4096);
            if (!(j & 1)) j++;
            if (j < bsz && bw[j] != 0u) atomicOr(&fb, 1);
        }
        __syncthreads();
        if (threadIdx.x == 0) {
            g_is64_edge  = (fe == 0);
            g_is64_batch = (fb == 0);
            g_base_ctr = 0;
        }
    }
    int i = blockIdx.x * blockDim.x + threadIdx.x;
    int st = gridDim.x * blockDim.x;
    for (int j = i; j < NN; j += st) g_deg[j] = 0;
    for (int j = i; j < NG * HO; j += st) g_pool[j] = 0.f;
}

// ---------------- degree histogram (returns rank!) + batch convert ----------
__global__ void k_prep(const void* __restrict__ ep, const void* __restrict__ bp) {
    int e64 = g_is64_edge, b64 = g_is64_batch;
    long stride = (long)gridDim.x * blockDim.x;
    long i0 = (long)blockIdx.x * blockDim.x + threadIdx.x;
    if (e64) {
        const long long* p = (const long long*)ep;
        for (long i = i0; i < NE; i += stride)
            g_rank[i] = atomicAdd(&g_deg[(int)p[NE + i]], 1);
    } else {
        const int* p = (const int*)ep;
        for (long i = i0; i < NE; i += stride)
            g_rank[i] = atomicAdd(&g_deg[p[NE + i]], 1);
    }
    if (b64) {
        const long long* p = (const long long*)bp;
        for (long i = i0; i < NN; i += stride) g_batch[i] = (int)p[i];
    } else {
        const int* p = (const int*)bp;
        for (long i = i0; i < NN; i += stride) g_batch[i] = p[i];
    }
}

// ---------------- merged: unordered scan (blocks < SB) + weight fold --------
#define SCAN_BLOCKS 98
#define FOLD_ITEMS (DD * HH + HH + HH * HO)
__global__ void k_scan_fold(const float* __restrict__ l1w, const float* __restrict__ l1b,
                            const float* __restrict__ c1w, const float* __restrict__ c2w) {
    if (blockIdx.x < SCAN_BLOCKS) {
        __shared__ int s[1024];
        __shared__ int sbase;
        int t = threadIdx.x;
        int i = blockIdx.x * 1024 + t;
        int v = (i < NN) ? g_deg[i] : 0;
        s[t] = v;
        __syncthreads();
        for (int o = 1; o < 1024; o <<= 1) {
            int add = (t >= o) ? s[t - o] : 0;
            __syncthreads();
            if (t >= o) s[t] += add;
            __syncthreads();
        }
        if (t == 1023) sbase = atomicAdd(&g_base_ctr, s[1023]);
        __syncthreads();
        if (i < NN) {
            g_rowptr[i] = s[t] - v + sbase;
            g_dis[i] = rsqrtf((float)(v + 1));  // +1 for the self loop
        }
    } else {
        int idx = (blockIdx.x - SCAN_BLOCKS) * 1024 + threadIdx.x;
        if (idx < DD * HH) {
            int k = idx / HH, m = idx % HH;
            float s = 0.f;
            for (int j = 0; j < DD; j++) s += l1w[k * DD + j] * c1w[j * HH + m];
            g_W12T[m * DD + k] = __float2half(s);
        } else if (idx < DD * HH + HH) {
            int m = idx - DD * HH;
            float s = 0.f;
            for (int j = 0; j < DD; j++) s += l1b[j] * c1w[j * HH + m];
            g_b12[m] = s;
        } else if (idx < FOLD_ITEMS) {
            int j = idx - (DD * HH + HH);
            int k = j / HO, n = j % HO;
            g_W2T[n * DD + k] = __float2half(c2w[k * HO + n]);
        }
    }
}

// ---------------- CSR fill (atomic-free: pos = rowptr[dst] + rank) -----------
__global__ void k_fill(const void* __restrict__ ep) {
    int e64 = g_is64_edge;
    long stride = (long)gridDim.x * blockDim.x;
    long i0 = (long)blockIdx.x * blockDim.x + threadIdx.x;
    if (e64) {
        const long long* p = (const long long*)ep;
        for (long i = i0; i < NE; i += stride) {
            int s = (int)p[i];
            int d = (int)p[NE + i];
            g_col[g_rowptr[d] + g_rank[i]] = s;
        }
    } else {
        const int* p = (const int*)ep;
        for (long i = i0; i < NE; i += stride) {
            int s = p[i];
            int d = p[NE + i];
            g_col[g_rowptr[d] + g_rank[i]] = s;
        }
    }
}

// ---------------- HMMA GEMM: out[n][MOUT] = (A[n][128] @ W (+bias)) * dis[n]
// MODE 1: A = x (fp32), W = g_W12T, bias = g_b12, out = g_h2
// MODE 2: A = g_h3 (fp16), W = g_W2T, no bias,    out = g_h4
template <int MOUT, int MODE>
__global__ void __launch_bounds__(256) k_gemm(const float* __restrict__ x) {
    constexpr int ROWS = 64;
    constexpr int KPAD = 72;                 // 64 + 8 halves pad -> conflict-free
    constexpr int NW = MOUT / 4;             // warp n-width (32 or 16)
    constexpr int NT = NW / 8;               // n8-tiles per warp (4 or 2)
    __shared__ __half As[ROWS][KPAD];
    __shared__ __half Ws[MOUT][KPAD];

    int tid = threadIdx.x;
    int wid = tid >> 5, lane = tid & 31;
    int gid = lane >> 2, tg = lane & 3;
    int wm = wid >> 2, wn = wid & 3;         // 2 x 4 warp grid
    int row0 = blockIdx.x * ROWS;
    __half* out = (MODE == 1) ? g_h2 : g_h4;
    const __half* WT = (MODE == 1) ? g_W12T : g_W2T;

    float acc[2][NT][4];
#pragma unroll
    for (int mt = 0; mt < 2; mt++)
#pragma unroll
        for (int nt = 0; nt < NT; nt++)
#pragma unroll
            for (int q = 0; q < 4; q++) acc[mt][nt][q] = 0.f;

#pragma unroll
    for (int ch = 0; ch < 2; ch++) {
        int k0 = ch * 64;
        // ---- load A chunk into smem (fp16) ----
        if (MODE == 1) {
#pragma unroll
            for (int idx = tid; idx < ROWS * 16; idx += 256) {
                int r = idx >> 4, q = idx & 15;
                int gr = row0 + r;
                float4 v = make_float4(0.f, 0.f, 0.f, 0.f);
                if (gr < NN) v = *(const float4*)&x[(size_t)gr * DD + k0 + q * 4];
                *(__half2*)&As[r][q * 4]     = __floats2half2_rn(v.x, v.y);
                *(__half2*)&As[r][q * 4 + 2] = __floats2half2_rn(v.z, v.w);
            }
        } else {
#pragma unroll
            for (int idx = tid; idx < ROWS * 8; idx += 256) {
                int r = idx >> 3, q = idx & 7;
                int gr = row0 + r;
                uint4 v = make_uint4(0u, 0u, 0u, 0u);
                if (gr < NN) v = *(const uint4*)&g_h3[(size_t)gr * HH + k0 + q * 8];
                *(uint4*)&As[r][q * 8] = v;
            }
        }
        // ---- load W^T chunk (already fp16 n-major) ----
#pragma unroll
        for (int idx = tid; idx < MOUT * 8; idx += 256) {
            int n = idx >> 3, q = idx & 7;
            *(uint4*)&Ws[n][q * 8] = *(const uint4*)&WT[n * DD + k0 + q * 8];
        }
        __syncthreads();
        // ---- 4 k16 steps ----
#pragma unroll
        for (int ks = 0; ks < 4; ks++) {
            int kk = ks * 16;
            unsigned af[2][4];
#pragma unroll
            for (int mt = 0; mt < 2; mt++) {
                int r = wm * 32 + mt * 16 + gid;
                af[mt][0] = *(unsigned*)&As[r][kk + tg * 2];
                af[mt][1] = *(unsigned*)&As[r + 8][kk + tg * 2];
                af[mt][2] = *(unsigned*)&As[r][kk + tg * 2 + 8];
                af[mt][3] = *(unsigned*)&As[r + 8][kk + tg * 2 + 8];
            }
            unsigned bf[NT][2];
#pragma unroll
            for (int nt = 0; nt < NT; nt++) {
                int n = wn * NW + nt * 8 + gid;
                bf[nt][0] = *(unsigned*)&Ws[n][kk + tg * 2];
                bf[nt][1] = *(unsigned*)&Ws[n][kk + tg * 2 + 8];
            }
#pragma unroll
            for (int mt = 0; mt < 2; mt++)
#pragma unroll
                for (int nt = 0; nt < NT; nt++)
                    mma16816(acc[mt][nt], af[mt], bf[nt]);
        }
        __syncthreads();
    }

    // ---- epilogue: +bias, *dis, fp16 store ----
#pragma unroll
    for (int mt = 0; mt < 2; mt++) {
        int r_lo = row0 + wm * 32 + mt * 16 + gid;
        int r_hi = r_lo + 8;
        float dlo = (r_lo < NN) ? g_dis[r_lo] : 0.f;
        float dhi = (r_hi < NN) ? g_dis[r_hi] : 0.f;
#pragma unroll
        for (int nt = 0; nt < NT; nt++) {
            int n = wn * NW + nt * 8 + tg * 2;
            float b0 = 0.f, b1 = 0.f;
            if (MODE == 1) { b0 = g_b12[n]; b1 = g_b12[n + 1]; }
            if (r_lo < NN)
                *(__half2*)&out[(size_t)r_lo * MOUT + n] =
                    __floats2half2_rn((acc[mt][nt][0] + b0) * dlo,
                                      (acc[mt][nt][1] + b1) * dlo);
            if (r_hi < NN)
                *(__half2*)&out[(size_t)r_hi * MOUT + n] =
                    __floats2half2_rn((acc[mt][nt][2] + b0) * dhi,
                                      (acc[mt][nt][3] + b1) * dhi);
        }
    }
}

// ---------------- aggregation 1 (gather-sum fp16, 128 feats) + bias/drop/relu
__global__ void k_agg1(const float* __restrict__ c1b, const float* __restrict__ du) {
    int node = (blockIdx.x * blockDim.x + threadIdx.x) >> 5;
    int lane = threadIdx.x & 31;
    if (node >= NN) return;
    float di = g_dis[node];
    size_t base = (size_t)node * HH + lane * 4;
    uint2 rs = *(const uint2*)&g_h2[base];  // self loop term
    float2 f0 = __half22float2(*(__half2*)&rs.x);
    float2 f1 = __half22float2(*(__half2*)&rs.y);
    float ax = f0.x, ay = f0.y, az = f1.x, aw = f1.y;
    int b = g_rowptr[node];
    int e = b + g_deg[node];
    int t = b;
    for (; t + 8 <= e; t += 8) {
        int si[8];
#pragma unroll
        for (int q = 0; q < 8; q++) si[q] = g_col[t + q];
        uint2 r[8];
#pragma unroll
        for (int q = 0; q < 8; q++)
            r[q] = *(const uint2*)&g_h2[(size_t)si[q] * HH + lane * 4];
#pragma unroll
        for (int q = 0; q < 8; q++) {
            float2 a = __half22float2(*(__half2*)&r[q].x);
            float2 bb = __half22float2(*(__half2*)&r[q].y);
            ax += a.x; ay += a.y; az += bb.x; aw += bb.y;
        }
    }
    for (; t + 4 <= e; t += 4) {
        int s0 = g_col[t], s1 = g_col[t + 1], s2 = g_col[t + 2], s3 = g_col[t + 3];
        uint2 r0 = *(const uint2*)&g_h2[(size_t)s0 * HH + lane * 4];
        uint2 r1 = *(const uint2*)&g_h2[(size_t)s1 * HH + lane * 4];
        uint2 r2 = *(const uint2*)&g_h2[(size_t)s2 * HH + lane * 4];
        uint2 r3 = *(const uint2*)&g_h2[(size_t)s3 * HH + lane * 4];
        float2 a0 = __half22float2(*(__half2*)&r0.x), b0 = __half22float2(*(__half2*)&r0.y);
        float2 a1 = __half22float2(*(__half2*)&r1.x), b1 = __half22float2(*(__half2*)&r1.y);
        float2 a2 = __half22float2(*(__half2*)&r2.x), b2 = __half22float2(*(__half2*)&r2.y);
        float2 a3 = __half22float2(*(__half2*)&r3.x), b3 = __half22float2(*(__half2*)&r3.y);
        ax += (a0.x + a1.x) + (a2.x + a3.x);
        ay += (a0.y + a1.y) + (a2.y + a3.y);
        az += (b0.x + b1.x) + (b2.x + b3.x);
        aw += (b0.y + b1.y) + (b2.y + b3.y);
    }
    for (; t < e; t++) {
        int s = g_col[t];
        uint2 r = *(const uint2*)&g_h2[(size_t)s * HH + lane * 4];
        float2 a = __half22float2(*(__half2*)&r.x);
        float2 bq = __half22float2(*(__half2*)&r.y);
        ax += a.x; ay += a.y; az += bq.x; aw += bq.y;
    }
    int c0 = lane * 4;
    float4 bb = *(const float4*)&c1b[c0];
    float4 dd = *(const float4*)&du[(size_t)node * DD + c0];
    float o[4] = {di * ax + bb.x, di * ay + bb.y, di * az + bb.z, di * aw + bb.w};
    float d4[4] = {dd.x, dd.y, dd.z, dd.w};
#pragma unroll
    for (int q = 0; q < 4; q++) {
        float val = (d4[q] >= 0.5f) ? o[q] * 2.f : 0.f;
        o[q] = fmaxf(val, 0.f);
    }
    uint2 pk;
    __half2 h0 = __floats2half2_rn(o[0], o[1]);
    __half2 h1 = __floats2half2_rn(o[2], o[3]);
    pk.x = *(unsigned*)&h0;
    pk.y = *(unsigned*)&h1;
    *(uint2*)&g_h3[base] = pk;
}

// ---------------- aggregation 2 (fp16, 64 feats) + bias + fused mean-pool ----
#define NPW 8
__global__ void k_agg2(const float* __restrict__ c2b) {
    int w = (blockIdx.x * blockDim.x + threadIdx.x) >> 5;
    int lane = threadIdx.x & 31;
    int n0 = w * NPW;
    if (n0 >= NN) return;
    int n1 = min(n0 + NPW, NN);
    int c0 = lane * 2;
    float b0 = c2b[c0], b1 = c2b[c0 + 1];
    int curg = -1;
    float s0 = 0.f, s1 = 0.f;
    for (int node = n0; node < n1; node++) {
        float di = g_dis[node];
        float2 v = __half22float2(*(const __half2*)&g_h4[(size_t)node * HO + c0]);
        float a0 = v.x, a1 = v.y;
        int b = g_rowptr[node];
        int e = b + g_deg[node];
        int t = b;
        for (; t + 8 <= e; t += 8) {
            int si[8];
#pragma unroll
            for (int q = 0; q < 8; q++) si[q] = g_col[t + q];
            float2 u[8];
#pragma unroll
            for (int q = 0; q < 8; q++)
                u[q] = __half22float2(*(const __half2*)&g_h4[(size_t)si[q] * HO + c0]);
#pragma unroll
            for (int q = 0; q < 8; q++) { a0 += u[q].x; a1 += u[q].y; }
        }
        for (; t + 4 <= e; t += 4) {
            int x0 = g_col[t], x1 = g_col[t + 1], x2 = g_col[t + 2], x3 = g_col[t + 3];
            float2 u0 = __half22float2(*(const __half2*)&g_h4[(size_t)x0 * HO + c0]);
            float2 u1 = __half22float2(*(const __half2*)&g_h4[(size_t)x1 * HO + c0]);
            float2 u2 = __half22float2(*(const __half2*)&g_h4[(size_t)x2 * HO + c0]);
            float2 u3 = __half22float2(*(const __half2*)&g_h4[(size_t)x3 * HO + c0]);
            a0 += (u0.x + u1.x) + (u2.x + u3.x);
            a1 += (u0.y + u1.y) + (u2.y + u3.y);
        }
        for (; t < e; t++) {
            int s = g_col[t];
            float2 u = __half22float2(*(const __half2*)&g_h4[(size_t)s * HO + c0]);
            a0 += u.x; a1 += u.y;
        }
        float v0 = di * a0 + b0;
        float v1 = di * a1 + b1;
        int g = g_batch[node];
        if (g != curg) {
            if (curg >= 0) {
                atomicAdd(&g_pool[curg * HO + c0], s0);
                atomicAdd(&g_pool[curg * HO + c0 + 1], s1);
            }
            curg = g;
            s0 = 0.f; s1 = 0.f;
        }
        s0 += v0; s1 += v1;
    }
    if (curg >= 0) {
        atomicAdd(&g_pool[curg * HO + c0], s0);
        atomicAdd(&g_pool[curg * HO + c0 + 1], s1);
    }
}

// ---------------- final: (pool / cnt) @ lin2_w + lin2_b ---------------------
__device__ __forceinline__ int d_lower_bound(int g) {
    int lo = 0, hi = NN;
    while (lo < hi) {
        int m = (lo + hi) >> 1;
        if (g_batch[m] < g) lo = m + 1; else hi = m;
    }
    return lo;
}

__global__ void k_final(const float* __restrict__ w2, const float* __restrict__ b2,
                        float* __restrict__ out) {
    int idx = blockIdx.x * blockDim.x + threadIdx.x;
    if (idx >= NG * NCLS) return;
    int g = idx / NCLS, c = idx % NCLS;
    int cnt = d_lower_bound(g + 1) - d_lower_bound(g);
    float cf = (float)cnt;
    if (cf < 1.f) cf = 1.f;
    float inv = 1.f / cf;
    float s = 0.f;
    for (int j = 0; j < HO; j++) s += g_pool[g * HO + j] * inv * w2[j * NCLS + c];
    out[idx] = s + b2[c];
}

// ---------------- host launcher --------------------------------------------
extern "C" void kernel_launch(void* const* d_in, const int* in_sizes, int n_in,
                              void* d_out, int out_size) {
    const float* x = (const float*)d_in[0];
    const void* edge = d_in[1];
    const void* batch = d_in[2];
    int off = (n_in >= 13 && in_sizes[3] == 1) ? 1 : 0;
    const float* drop_u = (const float*)d_in[3 + off];
    const float* l1w = (const float*)d_in[4 + off];
    const float* l1b = (const float*)d_in[5 + off];
    const float* c1w = (const float*)d_in[6 + off];
    const float* c1b = (const float*)d_in[7 + off];
    const float* c2w = (const float*)d_in[8 + off];
    const float* c2b = (const float*)d_in[9 + off];
    const float* l2w = (const float*)d_in[10 + off];
    const float* l2b = (const float*)d_in[11 + off];
    float* out = (float*)d_out;
    long esz = in_sizes[1];
    long bsz = in_sizes[2];

    k_detect_init<<<256, 256>>>((const unsigned int*)edge, esz,
                                (const unsigned int*)batch, bsz);
    k_prep<<<2048, 256>>>(edge, batch);
    {
        int fold_blocks = (FOLD_ITEMS + 1023) / 1024;
        k_scan_fold<<<SCAN_BLOCKS + fold_blocks, 1024>>>(l1w, l1b, c1w, c2w);
    }
    k_fill<<<2048, 256>>>(edge);
    k_gemm<HH, 1><<<(NN + 63) / 64, 256>>>(x);
    k_agg1<<<(NN + 7) / 8, 256>>>(c1b, drop_u);
    k_gemm<HO, 2><<<(NN + 63) / 64, 256>>>(nullptr);
    {
        int warps = (NN + NPW - 1) / NPW;
        int blocks = (warps + 7) / 8;
        k_agg2<<<blocks, 256>>>(c2b);
    }
    k_final<<<(NG * NCLS + 255) / 256, 256>>>(l2w, l2b, out);
    (void)out_size;
}